// round 4
// baseline (speedup 1.0000x reference)
#include <cuda_runtime.h>
#include <cstdint>

// ResRnn: 1024 sequential steps of
//   s      = [x_t, stream[0:960]]                     (shift-in)
//   h      = |s @ W1^T + b1|
//   stream = 0.97*s + 0.03*(h @ W2^T + b2)
// out = stream[:, 960:1024] after last step.
//
// Persistent kernel, 128 CTAs. CTA c owns rows [8c, 8c+8) of W1 and W2 in
// SMEM (transposed, fp32). State S and hidden H live in __device__ globals
// laid out [k][batch] so warp-lane = batch gives coalesced exchange traffic.
// Two device-wide epoch barriers per step (monotonic epoch => safe across
// CUDA-graph replays, counter reset by last arriver each barrier).

#define SEQ   1024
#define BATCH 256
#define INSZ  64
#define SSZ   1024
#define OUTSZ 64
#define NCTA  128
#define RPC   8      // W rows per CTA
#define NTHR  512    // 16 warps: 8 warps per K-half, warp covers 32 batch rows

__device__ float g_S[2][SSZ][BATCH];   // double-buffered shifted stream, [k][b]
__device__ float g_H[SSZ][BATCH];      // hidden activations, [i][b]
__device__ unsigned g_ctr;
__device__ volatile unsigned g_epoch;

__device__ __forceinline__ void gbar(unsigned ep0, unsigned idx) {
    __syncthreads();
    if (threadIdx.x == 0) {
        __threadfence();                       // publish my CTA's writes
        unsigned old = atomicAdd(&g_ctr, 1u);
        if (old == NCTA - 1u) {
            g_ctr = 0u;                        // all arrived; safe to reset
            __threadfence();                   // reset visible before release
            atomicAdd((unsigned*)&g_epoch, 1u);
        } else {
            while ((unsigned)(g_epoch - ep0) < idx) { }
        }
        __threadfence();                       // acquire others' writes
    }
    __syncthreads();
}

__global__ __launch_bounds__(NTHR, 1)
void resrnn_kernel(const float* __restrict__ x,
                   const float* __restrict__ W1,
                   const float* __restrict__ b1,
                   const float* __restrict__ W2,
                   const float* __restrict__ b2,
                   float* __restrict__ out)
{
    extern __shared__ float smem[];
    float* W1sT = smem;                        // [SSZ][RPC]  W1[i0+r][k] at [k*RPC+r]
    float* W2sT = smem + SSZ * RPC;            // [SSZ][RPC]
    float* red  = smem + 2 * SSZ * RPC;        // [BATCH][9]  (pad 9: conflict-free)
    float* b1s  = red + BATCH * 9;             // [RPC]
    float* b2s  = b1s + RPC;                   // [RPC]

    const int tid = threadIdx.x;
    const int cta = blockIdx.x;
    const int i0  = cta * RPC;

    const unsigned ep0 = g_epoch;              // read before first arrive (uniform)

    // Stage W slices (transposed so 2x LDS.128 per k yields all 8 row values).
    for (int idx = tid; idx < RPC * SSZ; idx += NTHR) {
        int r = idx >> 10, k = idx & (SSZ - 1);
        W1sT[k * RPC + r] = W1[(size_t)(i0 + r) * SSZ + k];
        W2sT[k * RPC + r] = W2[(size_t)(i0 + r) * SSZ + k];
    }
    if (tid < RPC) { b1s[tid] = b1[i0 + tid]; b2s[tid] = b2[i0 + tid]; }

    // Init S buffer 0 with the step-0 shifted stream: [x_0, zeros].
    for (int idx = tid; idx < RPC * BATCH; idx += NTHR) {
        int r = idx >> 8, b = idx & (BATCH - 1);
        int kk = i0 + r;
        g_S[0][kk][b] = (kk < INSZ) ? x[(size_t)b * INSZ + kk] : 0.0f;
    }

    unsigned bc = 0;
    gbar(ep0, ++bc);

    const int wid  = tid >> 5, lane = tid & 31;
    const int wg   = wid >> 3;                 // K-half: 0 or 1
    const int w8   = wid & 7;
    const int b    = w8 * 32 + lane;           // batch index (coalesced per warp)
    const int k0   = wg * (SSZ / 2);

    const float p = 0.97f;
    const float q = 1.0f - 0.97f;

    for (int t = 0; t < SEQ; ++t) {
        const float* __restrict__ Scur = &g_S[t & 1][0][0];
        float*       __restrict__ Snxt = &g_S[(t + 1) & 1][0][0];

        // ---------------- Phase 1: H[i0+r][b] = |dot(s, W1 row) + b1| -------
        {
            float acc[RPC];
#pragma unroll
            for (int r = 0; r < RPC; ++r) acc[r] = 0.0f;
            const float*  sp = Scur + (size_t)k0 * BATCH + b;
            const float4* wp = (const float4*)(W1sT + k0 * RPC);
#pragma unroll 8
            for (int k = 0; k < SSZ / 2; ++k) {
                float  sv = sp[(size_t)k * BATCH];
                float4 wa = wp[2 * k];
                float4 wb = wp[2 * k + 1];
                acc[0] += sv * wa.x; acc[1] += sv * wa.y;
                acc[2] += sv * wa.z; acc[3] += sv * wa.w;
                acc[4] += sv * wb.x; acc[5] += sv * wb.y;
                acc[6] += sv * wb.z; acc[7] += sv * wb.w;
            }
            if (wg == 1) {
#pragma unroll
                for (int r = 0; r < RPC; ++r) red[b * 9 + r] = acc[r];
            }
            __syncthreads();
            if (wg == 0) {
#pragma unroll
                for (int r = 0; r < RPC; ++r) {
                    float v = fabsf(acc[r] + red[b * 9 + r] + b1s[r]);
                    g_H[i0 + r][b] = v;
                }
            }
        }
        gbar(ep0, ++bc);

        // ---- Phase 2: s_new = p*s + q*(dot(h, W2 row) + b2), shift-write ---
        {
            float acc[RPC];
#pragma unroll
            for (int r = 0; r < RPC; ++r) acc[r] = 0.0f;
            const float*  hp = &g_H[0][0] + (size_t)k0 * BATCH + b;
            const float4* wp = (const float4*)(W2sT + k0 * RPC);
#pragma unroll 8
            for (int k = 0; k < SSZ / 2; ++k) {
                float  hv = hp[(size_t)k * BATCH];
                float4 wa = wp[2 * k];
                float4 wb = wp[2 * k + 1];
                acc[0] += hv * wa.x; acc[1] += hv * wa.y;
                acc[2] += hv * wa.z; acc[3] += hv * wa.w;
                acc[4] += hv * wb.x; acc[5] += hv * wb.y;
                acc[6] += hv * wb.z; acc[7] += hv * wb.w;
            }
            if (wg == 1) {
#pragma unroll
                for (int r = 0; r < RPC; ++r) red[b * 9 + r] = acc[r];
            }
            __syncthreads();
            if (wg == 0) {
#pragma unroll
                for (int r = 0; r < RPC; ++r) {
                    int j = i0 + r;
                    float snew = p * Scur[(size_t)j * BATCH + b]
                               + q * (acc[r] + red[b * 9 + r] + b2s[r]);
                    // shift: next step's s[j+64] = stream_new[j]
                    if (j < SSZ - INSZ)
                        Snxt[(size_t)(j + INSZ) * BATCH + b] = snew;
                    if (t == SEQ - 1 && j >= SSZ - OUTSZ)
                        out[b * OUTSZ + (j - (SSZ - OUTSZ))] = snew;
                }
            }
            // inject x_{t+1} into next buffer rows [0, 64) (idle wg==1 warps)
            if (i0 < INSZ && t + 1 < SEQ && wg == 1) {
#pragma unroll
                for (int r = 0; r < RPC; ++r) {
                    int kk = i0 + r;
                    Snxt[(size_t)kk * BATCH + b] =
                        x[(size_t)(t + 1) * BATCH * INSZ + (size_t)b * INSZ + kk];
                }
            }
        }
        gbar(ep0, ++bc);
    }
}

extern "C" void kernel_launch(void* const* d_in, const int* in_sizes, int n_in,
                              void* d_out, int out_size) {
    (void)in_sizes; (void)n_in; (void)out_size;
    const float* x  = (const float*)d_in[0];
    const float* W1 = (const float*)d_in[1];
    const float* b1 = (const float*)d_in[2];
    const float* W2 = (const float*)d_in[3];
    const float* b2 = (const float*)d_in[4];

    const size_t smem_bytes =
        (size_t)(2 * SSZ * RPC + BATCH * 9 + 2 * RPC) * sizeof(float);  // ~74.8 KB
    cudaFuncSetAttribute(resrnn_kernel,
                         cudaFuncAttributeMaxDynamicSharedMemorySize,
                         (int)smem_bytes);
    resrnn_kernel<<<NCTA, NTHR, smem_bytes>>>(x, W1, b1, W2, b2, (float*)d_out);
}